// round 15
// baseline (speedup 1.0000x reference)
#include <cuda_runtime.h>
#include <cuda_fp16.h>
#include <math.h>
#include <stdint.h>

// Problem constants
constexpr int L    = 3072;
constexpr int D    = 1024;
constexpr int H    = 16;
constexpr int HD   = 64;
constexpr int SCTX = 512;
constexpr int DFF  = 4096;
constexpr int NB   = 2;

// ---------------- scratch (static device arrays; no cudaMalloc allowed) ----
__device__ __half g_hx [(size_t)L * D];        // LN outputs (GEMM A, fp16)
__device__ float  g_q  [(size_t)L * D];
__device__ float  g_k  [(size_t)L * D];
__device__ float  g_v  [(size_t)L * D];
__device__ __half g_oh [(size_t)L * D];        // attention outputs (GEMM A, fp16)
__device__ float  g_ck [(size_t)SCTX * D];
__device__ float  g_cv [(size_t)SCTX * D];
__device__ __half g_hb [(size_t)L * DFF];      // GELU outputs (GEMM A, fp16)
__device__ float  g_kt [(size_t)H * HD * L];   // K^T [h][d][l] (tf32 attention)
__device__ __half g_w  [(size_t)16 * D * D];   // fp16-rounded weights, one iter
__device__ __half g_ctx[(size_t)SCTX * D];     // fp16-rounded context
__device__ float  g_mods[6 * D];

enum { EP_STORE = 0, EP_GELU = 1, EP_RESID = 2, EP_RESID_GATE = 3 };

__device__ __forceinline__ uint32_t f2tf(float x) {
    uint32_t r;
    asm("cvt.rna.tf32.f32 %0, %1;" : "=r"(r) : "f"(x));
    return r;
}
__device__ __forceinline__ float f2tf_f(float x) { return __uint_as_float(f2tf(x)); }

// tf32 mma (attention)
__device__ __forceinline__ void mma_tf32(float c[4], uint32_t a0, uint32_t a1,
                                         uint32_t a2, uint32_t a3,
                                         uint32_t b0, uint32_t b1) {
    asm volatile(
        "mma.sync.aligned.m16n8k8.row.col.f32.tf32.tf32.f32 "
        "{%0,%1,%2,%3}, {%4,%5,%6,%7}, {%8,%9}, {%0,%1,%2,%3};"
        : "+f"(c[0]), "+f"(c[1]), "+f"(c[2]), "+f"(c[3])
        : "r"(a0), "r"(a1), "r"(a2), "r"(a3), "r"(b0), "r"(b1));
}

// fp16 mma (GEMM): m16n8k16, f32 accumulate
__device__ __forceinline__ void mma_f16(float c[4], uint32_t a0, uint32_t a1,
                                        uint32_t a2, uint32_t a3,
                                        uint32_t b0, uint32_t b1) {
    asm volatile(
        "mma.sync.aligned.m16n8k16.row.col.f32.f16.f16.f32 "
        "{%0,%1,%2,%3}, {%4,%5,%6,%7}, {%8,%9}, {%0,%1,%2,%3};"
        : "+f"(c[0]), "+f"(c[1]), "+f"(c[2]), "+f"(c[3])
        : "r"(a0), "r"(a1), "r"(a2), "r"(a3), "r"(b0), "r"(b1));
}

__device__ __forceinline__ void cp_async16(uint32_t saddr, const void* gaddr) {
    asm volatile("cp.async.cg.shared.global [%0], [%1], 16;\n"
                 :: "r"(saddr), "l"(gaddr));
}
__device__ __forceinline__ void cp_commit() {
    asm volatile("cp.async.commit_group;\n");
}
template <int N>
__device__ __forceinline__ void cp_wait() {
    asm volatile("cp.async.wait_group %0;\n" :: "n"(N));
}

// ---------------------------------------------------------------------------
// Weight pre-round: 10 per-iter weight slices -> g_w, fp16 (RN).
// ---------------------------------------------------------------------------
__global__ void __launch_bounds__(256) round_w10(
    const float* s0, const float* s1, const float* s2, const float* s3,
    const float* s4, const float* s5, const float* s6, const float* s7,
    const float* s8, const float* s9, __half* dst)
{
    const int z = blockIdx.z;
    const float* src;
    size_t cnt, off;
    const size_t DD = (size_t)D * D;
    switch (z) {
        case 0: src = s0; cnt = DD;     off = 0;       break;
        case 1: src = s1; cnt = DD;     off = DD;      break;
        case 2: src = s2; cnt = DD;     off = 2 * DD;  break;
        case 3: src = s3; cnt = DD;     off = 3 * DD;  break;
        case 4: src = s4; cnt = DD;     off = 4 * DD;  break;
        case 5: src = s5; cnt = DD;     off = 5 * DD;  break;
        case 6: src = s6; cnt = DD;     off = 6 * DD;  break;
        case 7: src = s7; cnt = DD;     off = 7 * DD;  break;
        case 8: src = s8; cnt = 4 * DD; off = 8 * DD;  break;
        default: src = s9; cnt = 4 * DD; off = 12 * DD; break;
    }
    const size_t i = ((size_t)blockIdx.x * 256 + threadIdx.x) * 4;
    if (i >= cnt) return;
    float4 v = *reinterpret_cast<const float4*>(src + i);
    __half2* d2 = reinterpret_cast<__half2*>(dst + off + i);
    d2[0] = __floats2half2_rn(v.x, v.y);
    d2[1] = __floats2half2_rn(v.z, v.w);
}

// context round to fp16
__global__ void __launch_bounds__(256) round_arr(
    const float* __restrict__ src, __half* __restrict__ dst, size_t n4)
{
    const size_t i = ((size_t)blockIdx.x * 256 + threadIdx.x) * 4;
    if (i >= n4 * 4) return;
    float4 v = *reinterpret_cast<const float4*>(src + i);
    __half2* d2 = reinterpret_cast<__half2*>(dst + i);
    d2[0] = __floats2half2_rn(v.x, v.y);
    d2[1] = __floats2half2_rn(v.z, v.w);
}

// ---------------------------------------------------------------------------
// FP16 tensor-core GEMM (m16n8k16), 4-stage cp.async, BK=32 halves.
// 256 threads = 8 warps (2M x 4N), warp tile 64x32.
// Smem rows: 32 halves + 8 pad = 20 words; bank map (20*qr+qc)&31 injective
// over the warp -> conflict-free fragment LDS. Per-z A/M (fused launches).
// C dtype per mode: EP_GELU -> half, others -> float.
// ---------------------------------------------------------------------------
constexpr int GSTAGES = 4;
constexpr int GBKH    = 32;                          // halves per k-tile
constexpr int GSW     = 20;                          // words per row (16 + 4 pad)
constexpr int GTILE_W = 128 * GSW;                   // words per matrix tile
constexpr int GEMM_SMEM = 2 * GSTAGES * GTILE_W * 4; // 81920 bytes

__global__ void __launch_bounds__(256, 2) gemm_f16(
    const __half* __restrict__ A0, const __half* __restrict__ A1,
    const __half* __restrict__ A2,
    const __half* __restrict__ W0, const __half* __restrict__ W1,
    const __half* __restrict__ W2,
    const float* __restrict__ bias, const float* __restrict__ gate,
    void* __restrict__ C0, void* __restrict__ C1, void* __restrict__ C2,
    int M0, int M1, int M2, int N, int K, int mode)
{
    extern __shared__ float smem[];                  // word-addressed
    float* As = smem;
    float* Bs = smem + GSTAGES * GTILE_W;

    const __half* A = (blockIdx.z == 0) ? A0 : (blockIdx.z == 1) ? A1 : A2;
    const __half* W = (blockIdx.z == 0) ? W0 : (blockIdx.z == 1) ? W1 : W2;
    void*         C = (blockIdx.z == 0) ? C0 : (blockIdx.z == 1) ? C1 : C2;
    const int     M = (blockIdx.z == 0) ? M0 : (blockIdx.z == 1) ? M1 : M2;

    const int m0 = blockIdx.y * 128;
    if (m0 >= M) return;
    const int n0 = blockIdx.x * 128;

    const int tid  = threadIdx.x;
    const int lane = tid & 31;
    const int warp = tid >> 5;
    const int mwb  = (warp & 1) * 64;
    const int nwb  = (warp >> 1) * 32;
    const int qr   = lane >> 2;
    const int qc   = lane & 3;

    const uint32_t sA0 = (uint32_t)__cvta_generic_to_shared(As);
    const uint32_t sB0 = (uint32_t)__cvta_generic_to_shared(Bs);

    // loader: 512 16B-chunks (8 halves) per matrix per tile; 2 per thread.
    const int lrow = tid >> 1;            // 0..127
    const int lc0  = (tid & 1) * 2;       // chunk 0/2

    float acc[4][4][4];
#pragma unroll
    for (int i = 0; i < 4; i++)
#pragma unroll
        for (int j = 0; j < 4; j++)
#pragma unroll
            for (int e = 0; e < 4; e++) acc[i][j][e] = 0.f;

    const int nT = K / GBKH;

    auto ld_stage = [&](int slot, int t) {
        const int kb = t * GBKH;          // in halves
#pragma unroll
        for (int i = 0; i < 2; i++) {
            const int c = lc0 + i;
            const uint32_t off = (uint32_t)((slot * 128 + lrow) * GSW + c * 4) * 4u;
            cp_async16(sA0 + off, &A[(size_t)(m0 + lrow) * K + kb + c * 8]);
            cp_async16(sB0 + off, &W[(size_t)(n0 + lrow) * K + kb + c * 8]);
        }
    };

#pragma unroll
    for (int s = 0; s < GSTAGES - 1; s++) {
        if (s < nT) ld_stage(s, s);
        cp_commit();
    }

    int slot = 0;
    for (int t = 0; t < nT; t++) {
        cp_wait<GSTAGES - 2>();
        __syncthreads();

        {
            int ns = slot + GSTAGES - 1; if (ns >= GSTAGES) ns -= GSTAGES;
            if (t + GSTAGES - 1 < nT) ld_stage(ns, t + GSTAGES - 1);
            cp_commit();
        }

        const float* At = As + slot * GTILE_W + mwb * GSW;
        const float* Bt = Bs + slot * GTILE_W + nwb * GSW;

#pragma unroll
        for (int ks = 0; ks < 2; ks++) {
            const int kk = ks * 8;        // word offset of this k16 step
            uint32_t afr[4][4], bfr[4][2];
#pragma unroll
            for (int mt = 0; mt < 4; mt++) {
                const int mb = mt * 16;
                afr[mt][0] = __float_as_uint(At[(mb + qr    ) * GSW + kk + qc    ]);
                afr[mt][1] = __float_as_uint(At[(mb + qr + 8) * GSW + kk + qc    ]);
                afr[mt][2] = __float_as_uint(At[(mb + qr    ) * GSW + kk + qc + 4]);
                afr[mt][3] = __float_as_uint(At[(mb + qr + 8) * GSW + kk + qc + 4]);
            }
#pragma unroll
            for (int nt = 0; nt < 4; nt++) {
                const int nb = nt * 8;
                bfr[nt][0] = __float_as_uint(Bt[(nb + qr) * GSW + kk + qc    ]);
                bfr[nt][1] = __float_as_uint(Bt[(nb + qr) * GSW + kk + qc + 4]);
            }
#pragma unroll
            for (int mt = 0; mt < 4; mt++)
#pragma unroll
                for (int nt = 0; nt < 4; nt++)
                    mma_f16(acc[mt][nt], afr[mt][0], afr[mt][1], afr[mt][2],
                            afr[mt][3], bfr[nt][0], bfr[nt][1]);
        }

        if (++slot >= GSTAGES) slot = 0;
    }

#pragma unroll
    for (int mt = 0; mt < 4; mt++) {
#pragma unroll
        for (int nt = 0; nt < 4; nt++) {
#pragma unroll
            for (int half_ = 0; half_ < 2; half_++) {
                const int r = m0 + mwb + mt * 16 + qr + half_ * 8;
#pragma unroll
                for (int e = 0; e < 2; e++) {
                    const int c = n0 + nwb + nt * 8 + 2 * qc + e;
                    float val = acc[mt][nt][half_ * 2 + e];
                    val += bias ? bias[c] : 0.f;
                    const size_t idx = (size_t)r * N + c;
                    if (mode == EP_STORE) {
                        ((float*)C)[idx] = val;
                    } else if (mode == EP_GELU) {
                        ((__half*)C)[idx] = __float2half_rn(
                            0.5f * val * (1.f + erff(val * 0.70710678118654752f)));
                    } else if (mode == EP_RESID) {
                        ((float*)C)[idx] += val;
                    } else {
                        ((float*)C)[idx] += gate[c] * val;
                    }
                }
            }
        }
    }
}

// ---------------------------------------------------------------------------
// adaLN modulation GEMV
// ---------------------------------------------------------------------------
__global__ void __launch_bounds__(256) gemv_ada(
    const float* __restrict__ t, const float* __restrict__ Wt,
    const float* __restrict__ b, float* __restrict__ out)
{
    const int o    = blockIdx.x * 8 + (threadIdx.x >> 5);
    const int lane = threadIdx.x & 31;
    const float* wr = Wt + (size_t)o * D;
    float s = 0.f;
    for (int d = lane; d < D; d += 32) s = fmaf(t[d], wr[d], s);
#pragma unroll
    for (int off = 16; off; off >>= 1) s += __shfl_xor_sync(0xffffffffu, s, off);
    if (lane == 0) out[o] = s + b[o];
}

// ---------------------------------------------------------------------------
// LayerNorm (+ optional adaLN shift/scale); output fp16 (GEMM A-input)
// ---------------------------------------------------------------------------
__global__ void __launch_bounds__(256) ln_mod_kernel(
    const float* __restrict__ x, const float* __restrict__ mods,
    int sh_off, int sc_off, __half* __restrict__ y)
{
    __shared__ float red[8];
    __shared__ float bval;
    const int row = blockIdx.x;
    const int t = threadIdx.x;
    const float* xr = x + (size_t)row * D;

    float v[4];
    float s = 0.f;
#pragma unroll
    for (int j = 0; j < 4; j++) { v[j] = xr[t + j * 256]; s += v[j]; }
#pragma unroll
    for (int off = 16; off; off >>= 1) s += __shfl_xor_sync(0xffffffffu, s, off);
    if ((t & 31) == 0) red[t >> 5] = s;
    __syncthreads();
    if (t == 0) {
        float tot = 0.f;
        for (int j = 0; j < 8; j++) tot += red[j];
        bval = tot * (1.f / D);
    }
    __syncthreads();
    const float mean = bval;

    float vs = 0.f;
#pragma unroll
    for (int j = 0; j < 4; j++) { float d = v[j] - mean; vs = fmaf(d, d, vs); }
#pragma unroll
    for (int off = 16; off; off >>= 1) vs += __shfl_xor_sync(0xffffffffu, vs, off);
    if ((t & 31) == 0) red[t >> 5] = vs;
    __syncthreads();
    if (t == 0) {
        float tot = 0.f;
        for (int j = 0; j < 8; j++) tot += red[j];
        bval = rsqrtf(tot * (1.f / D) + 1e-6f);
    }
    __syncthreads();
    const float rstd = bval;

    __half* yr = y + (size_t)row * D;
#pragma unroll
    for (int j = 0; j < 4; j++) {
        const int d = t + j * 256;
        const float sc = mods ? mods[sc_off + d] : 0.f;
        const float sh = mods ? mods[sh_off + d] : 0.f;
        yr[d] = __float2half_rn((v[j] - mean) * rstd * (1.f + sc) + sh);
    }
}

// ---------------------------------------------------------------------------
// Fused RoPE(K) + transpose: k [L x D] -> kt [h][d][l], tf32-rounded.
// ---------------------------------------------------------------------------
__global__ void __launch_bounds__(256) rope_k_transpose(
    const float* __restrict__ k, const float* __restrict__ rope,
    float* __restrict__ KT)
{
    __shared__ float s[32][65];
    const int h  = blockIdx.y;
    const int l0 = blockIdx.x * 32;
    const int tx = threadIdx.x, ty = threadIdx.y;

#pragma unroll
    for (int jl = 0; jl < 4; jl++) {
        const int l  = ty + jl * 8;
        const int gl = l0 + l;
        const float v1 = k[(size_t)gl * D + h * HD + tx];
        const float v2 = k[(size_t)gl * D + h * HD + tx + 32];
        const float a1 = rope[gl * HD + tx];
        const float a2 = rope[gl * HD + tx + 32];
        s[l][tx]      = v1 * cosf(a1) - v2 * sinf(a1);
        s[l][tx + 32] = v2 * cosf(a2) + v1 * sinf(a2);
    }
    __syncthreads();

#pragma unroll
    for (int jd = 0; jd < 8; jd++) {
        const int d = ty + jd * 8;
        KT[(size_t)h * HD * L + (size_t)d * L + l0 + tx] = f2tf_f(s[tx][d]);
    }
}

// ---------------------------------------------------------------------------
// Plain K transpose (cross-attention; no rope)
// ---------------------------------------------------------------------------
__global__ void __launch_bounds__(256) transpose_k(
    const float* __restrict__ Kin, float* __restrict__ KT, int Lk)
{
    __shared__ float t[32][33];
    const int h  = blockIdx.z;
    const int d0 = blockIdx.y * 32;
    const int l0 = blockIdx.x * 32;
    const int tx = threadIdx.x, ty = threadIdx.y;
#pragma unroll
    for (int j = 0; j < 4; j++)
        t[ty + j * 8][tx] = Kin[(size_t)(l0 + ty + j * 8) * D + h * HD + d0 + tx];
    __syncthreads();
#pragma unroll
    for (int j = 0; j < 4; j++)
        KT[(size_t)h * HD * Lk + (size_t)(d0 + ty + j * 8) * Lk + l0 + tx] =
            f2tf_f(t[tx][ty + j * 8]);
}

// ---------------------------------------------------------------------------
// Tensor-core flash attention (tf32), cp.async overlap, 128 queries/block.
// Optional fused RoPE on Q. O output fp16 (GEMM A-input).
// ---------------------------------------------------------------------------
constexpr int ATTN_SMEM = (2 * 64 * 72 + 64 * 72 + 128 * 68) * 4;  // 90112 B

__global__ void __launch_bounds__(256, 2) attn_mma(
    const float* __restrict__ Q, const float* __restrict__ KT,
    const float* __restrict__ Vp, __half* __restrict__ O,
    const float* __restrict__ ropePtr, int Lk, float scale)
{
    extern __shared__ float sm[];
    float* Ks = sm;                    // [2][64][72]
    float* Vs = sm + 2 * 64 * 72;      // [64][72]
    float* Ps = sm + 3 * 64 * 72;      // [128][68]

    const int tid  = threadIdx.x;
    const int warp = tid >> 5;
    const int lane = tid & 31;
    const int qr = lane >> 2, qc = lane & 3;
    const int h  = blockIdx.y;
    const int q0 = blockIdx.x * 128;
    const int row0 = warp * 16;

    const float* KTh = KT + (size_t)h * HD * Lk;
    const uint32_t sKs = (uint32_t)__cvta_generic_to_shared(Ks);
    const uint32_t sVs = (uint32_t)__cvta_generic_to_shared(Vs);

    for (int i = tid; i < 64 * 16; i += 256) {
        const int r = i >> 4, c4 = (i & 15) * 4;
        cp_async16(sKs + (uint32_t)(r * 72 + c4) * 4u, &KTh[(size_t)r * Lk + c4]);
    }
    cp_commit();

    if (ropePtr) {
        for (int i = tid; i < 128 * 8; i += 256) {
            const int r = i >> 3, j4 = (i & 7) * 4;
            const int gl = q0 + r;
            float4 q1 = *reinterpret_cast<const float4*>(&Q[(size_t)gl * D + h * HD + j4]);
            float4 q2 = *reinterpret_cast<const float4*>(&Q[(size_t)gl * D + h * HD + j4 + 32]);
            float4 a1 = *reinterpret_cast<const float4*>(&ropePtr[gl * HD + j4]);
            float4 a2 = *reinterpret_cast<const float4*>(&ropePtr[gl * HD + j4 + 32]);
            float* d1 = &Ps[r * 68 + j4];
            float* d2 = &Ps[r * 68 + j4 + 32];
            d1[0] = (q1.x * cosf(a1.x) - q2.x * sinf(a1.x)) * scale;
            d1[1] = (q1.y * cosf(a1.y) - q2.y * sinf(a1.y)) * scale;
            d1[2] = (q1.z * cosf(a1.z) - q2.z * sinf(a1.z)) * scale;
            d1[3] = (q1.w * cosf(a1.w) - q2.w * sinf(a1.w)) * scale;
            d2[0] = (q2.x * cosf(a2.x) + q1.x * sinf(a2.x)) * scale;
            d2[1] = (q2.y * cosf(a2.y) + q1.y * sinf(a2.y)) * scale;
            d2[2] = (q2.z * cosf(a2.z) + q1.z * sinf(a2.z)) * scale;
            d2[3] = (q2.w * cosf(a2.w) + q1.w * sinf(a2.w)) * scale;
        }
    } else {
        for (int i = tid; i < 128 * 16; i += 256) {
            const int r = i >> 4, c4 = (i & 15) * 4;
            float4 qv = *reinterpret_cast<const float4*>(&Q[(size_t)(q0 + r) * D + h * HD + c4]);
            float* dst = &Ps[r * 68 + c4];
            dst[0] = qv.x * scale; dst[1] = qv.y * scale;
            dst[2] = qv.z * scale; dst[3] = qv.w * scale;
        }
    }
    __syncthreads();

    uint32_t qf[8][4];
#pragma unroll
    for (int ks = 0; ks < 8; ks++) {
        const int kk = ks * 8;
        qf[ks][0] = f2tf(Ps[(row0 + qr    ) * 68 + kk + qc    ]);
        qf[ks][1] = f2tf(Ps[(row0 + qr + 8) * 68 + kk + qc    ]);
        qf[ks][2] = f2tf(Ps[(row0 + qr    ) * 68 + kk + qc + 4]);
        qf[ks][3] = f2tf(Ps[(row0 + qr + 8) * 68 + kk + qc + 4]);
    }

    float m0 = -1e30f, m1 = -1e30f, l0 = 0.f, l1 = 0.f;
    float oacc[8][4];
#pragma unroll
    for (int nt = 0; nt < 8; nt++)
#pragma unroll
        for (int e = 0; e < 4; e++) oacc[nt][e] = 0.f;

    const int nTiles = Lk / 64;
    for (int ti = 0; ti < nTiles; ti++) {
        const int kt = ti * 64;
        float* Kb = Ks + (ti & 1) * 64 * 72;

        cp_wait<0>();
        __syncthreads();

        for (int i = tid; i < 64 * 16; i += 256) {
            const int r = i >> 4, c4 = (i & 15) * 4;
            cp_async16(sVs + (uint32_t)(r * 72 + c4) * 4u,
                       &Vp[(size_t)(kt + r) * D + h * HD + c4]);
        }
        cp_commit();
        if (ti + 1 < nTiles) {
            const uint32_t kb2 = sKs + (uint32_t)(((ti + 1) & 1) * 64 * 72) * 4u;
            for (int i = tid; i < 64 * 16; i += 256) {
                const int r = i >> 4, c4 = (i & 15) * 4;
                cp_async16(kb2 + (uint32_t)(r * 72 + c4) * 4u,
                           &KTh[(size_t)r * Lk + kt + 64 + c4]);
            }
        }
        cp_commit();

        float sf[8][4];
#pragma unroll
        for (int nt = 0; nt < 8; nt++)
#pragma unroll
            for (int e = 0; e < 4; e++) sf[nt][e] = 0.f;
#pragma unroll
        for (int ks = 0; ks < 8; ks++) {
            const int kk = ks * 8;
#pragma unroll
            for (int nt = 0; nt < 8; nt++) {
                const uint32_t b0 = __float_as_uint(Kb[(kk + qc    ) * 72 + nt * 8 + qr]);
                const uint32_t b1 = __float_as_uint(Kb[(kk + qc + 4) * 72 + nt * 8 + qr]);
                mma_tf32(sf[nt], qf[ks][0], qf[ks][1], qf[ks][2], qf[ks][3], b0, b1);
            }
        }

        float rmax0 = -1e30f, rmax1 = -1e30f;
#pragma unroll
        for (int nt = 0; nt < 8; nt++) {
            rmax0 = fmaxf(rmax0, fmaxf(sf[nt][0], sf[nt][1]));
            rmax1 = fmaxf(rmax1, fmaxf(sf[nt][2], sf[nt][3]));
        }
        rmax0 = fmaxf(rmax0, __shfl_xor_sync(0xffffffffu, rmax0, 1));
        rmax0 = fmaxf(rmax0, __shfl_xor_sync(0xffffffffu, rmax0, 2));
        rmax1 = fmaxf(rmax1, __shfl_xor_sync(0xffffffffu, rmax1, 1));
        rmax1 = fmaxf(rmax1, __shfl_xor_sync(0xffffffffu, rmax1, 2));

        const float mn0 = fmaxf(m0, rmax0);
        const float mn1 = fmaxf(m1, rmax1);
        const float a0 = __expf(m0 - mn0);
        const float a1 = __expf(m1 - mn1);
        float rs0 = 0.f, rs1 = 0.f;
#pragma unroll
        for (int nt = 0; nt < 8; nt++) {
            sf[nt][0] = __expf(sf[nt][0] - mn0);
            sf[nt][1] = __expf(sf[nt][1] - mn0);
            sf[nt][2] = __expf(sf[nt][2] - mn1);
            sf[nt][3] = __expf(sf[nt][3] - mn1);
            rs0 += sf[nt][0] + sf[nt][1];
            rs1 += sf[nt][2] + sf[nt][3];
        }
        rs0 += __shfl_xor_sync(0xffffffffu, rs0, 1);
        rs0 += __shfl_xor_sync(0xffffffffu, rs0, 2);
        rs1 += __shfl_xor_sync(0xffffffffu, rs1, 1);
        rs1 += __shfl_xor_sync(0xffffffffu, rs1, 2);
        l0 = l0 * a0 + rs0;
        l1 = l1 * a1 + rs1;
        m0 = mn0; m1 = mn1;
#pragma unroll
        for (int nt = 0; nt < 8; nt++) {
            oacc[nt][0] *= a0; oacc[nt][1] *= a0;
            oacc[nt][2] *= a1; oacc[nt][3] *= a1;
        }

        __syncwarp();
#pragma unroll
        for (int nt = 0; nt < 8; nt++) {
            float2 p0 = make_float2(f2tf_f(sf[nt][0]), f2tf_f(sf[nt][1]));
            float2 p1 = make_float2(f2tf_f(sf[nt][2]), f2tf_f(sf[nt][3]));
            *reinterpret_cast<float2*>(&Ps[(row0 + qr    ) * 68 + nt * 8 + 2 * qc]) = p0;
            *reinterpret_cast<float2*>(&Ps[(row0 + qr + 8) * 68 + nt * 8 + 2 * qc]) = p1;
        }
        __syncwarp();

        cp_wait<1>();
        __syncthreads();

#pragma unroll
        for (int ks = 0; ks < 8; ks++) {
            const int kk = ks * 8;
            const uint32_t pa0 = __float_as_uint(Ps[(row0 + qr    ) * 68 + kk + qc    ]);
            const uint32_t pa1 = __float_as_uint(Ps[(row0 + qr + 8) * 68 + kk + qc    ]);
            const uint32_t pa2 = __float_as_uint(Ps[(row0 + qr    ) * 68 + kk + qc + 4]);
            const uint32_t pa3 = __float_as_uint(Ps[(row0 + qr + 8) * 68 + kk + qc + 4]);
#pragma unroll
            for (int nt = 0; nt < 8; nt++) {
                const uint32_t b0 = f2tf(Vs[(kk + qc    ) * 72 + nt * 8 + qr]);
                const uint32_t b1 = f2tf(Vs[(kk + qc + 4) * 72 + nt * 8 + qr]);
                mma_tf32(oacc[nt], pa0, pa1, pa2, pa3, b0, b1);
            }
        }
    }

    // epilogue: O in fp16 (GEMM A-input)
    const float inv0 = 1.f / l0;
    const float inv1 = 1.f / l1;
#pragma unroll
    for (int nt = 0; nt < 8; nt++) {
        __half2 w0 = __floats2half2_rn(oacc[nt][0] * inv0, oacc[nt][1] * inv0);
        __half2 w1 = __floats2half2_rn(oacc[nt][2] * inv1, oacc[nt][3] * inv1);
        *reinterpret_cast<__half2*>(&O[(size_t)(q0 + row0 + qr    ) * D + h * HD + nt * 8 + 2 * qc]) = w0;
        *reinterpret_cast<__half2*>(&O[(size_t)(q0 + row0 + qr + 8) * D + h * HD + nt * 8 + 2 * qc]) = w1;
    }
}

// ---------------------------------------------------------------------------
extern "C" void kernel_launch(void* const* d_in, const int* in_sizes, int n_in,
                              void* d_out, int out_size)
{
    const float* x_in = (const float*)d_in[0];
    const float* ts   = (const float*)d_in[1];
    const float* ctx  = (const float*)d_in[2];
    const float* rope = (const float*)d_in[3];
    const float* adaW = (const float*)d_in[4];
    const float* adab = (const float*)d_in[5];
    const float* sqW  = (const float*)d_in[6];
    const float* skW  = (const float*)d_in[7];
    const float* svW  = (const float*)d_in[8];
    const float* soW  = (const float*)d_in[9];
    const float* sob  = (const float*)d_in[10];
    const float* cqW  = (const float*)d_in[11];
    const float* ckW  = (const float*)d_in[12];
    const float* cvW  = (const float*)d_in[13];
    const float* coW  = (const float*)d_in[14];
    const float* cob  = (const float*)d_in[15];
    const float* f1W  = (const float*)d_in[16];
    const float* f1b  = (const float*)d_in[17];
    const float* f2W  = (const float*)d_in[18];
    const float* f2b  = (const float*)d_in[19];

    float* x = (float*)d_out;

    __half *hx, *oh, *hb, *wh, *ctxh;
    float *q, *k, *v, *ckb, *cvb, *kt, *mods;
    cudaGetSymbolAddress((void**)&hx,   g_hx);
    cudaGetSymbolAddress((void**)&q,    g_q);
    cudaGetSymbolAddress((void**)&k,    g_k);
    cudaGetSymbolAddress((void**)&v,    g_v);
    cudaGetSymbolAddress((void**)&oh,   g_oh);
    cudaGetSymbolAddress((void**)&ckb,  g_ck);
    cudaGetSymbolAddress((void**)&cvb,  g_cv);
    cudaGetSymbolAddress((void**)&hb,   g_hb);
    cudaGetSymbolAddress((void**)&kt,   g_kt);
    cudaGetSymbolAddress((void**)&wh,   g_w);
    cudaGetSymbolAddress((void**)&ctxh, g_ctx);
    cudaGetSymbolAddress((void**)&mods, g_mods);

    cudaFuncSetAttribute(attn_mma, cudaFuncAttributeMaxDynamicSharedMemorySize, ATTN_SMEM);
    cudaFuncSetAttribute(gemm_f16, cudaFuncAttributeMaxDynamicSharedMemorySize, GEMM_SMEM);

    cudaMemcpyAsync(x, x_in, (size_t)L * D * sizeof(float), cudaMemcpyDeviceToDevice);

    const size_t DD = (size_t)D * D;
    const float scale = 0.125f; // 64^-0.5
    const dim3 gQKV(D   / 128, L / 128, 3);
    const dim3 gD  (D   / 128, L / 128, 1);
    const dim3 gDFF(DFF / 128, L / 128, 1);
    const dim3 gCQKV(D  / 128, L / 128, 3);
    const dim3 gAtt(L / 128, H);
    const dim3 gRKT(L / 32, H);
    const dim3 gTrC(SCTX / 32, HD / 32, H);
    const dim3 bTr(32, 8);
    const dim3 gRW((4 * DD) / 1024, 1, 10);

    // pre-round context once
    round_arr<<<(SCTX * D) / 1024, 256>>>(ctx, ctxh, (size_t)(SCTX * D) / 4);

    for (int i = 0; i < NB; i++) {
        const float* adaW_i = adaW + (size_t)i * 6 * DD;
        const float* adab_i = adab + (size_t)i * 6 * D;
        const float* sob_i  = sob  + (size_t)i * D;
        const float* cob_i  = cob  + (size_t)i * D;
        const float* f1b_i  = f1b  + (size_t)i * DFF;
        const float* f2b_i  = f2b  + (size_t)i * D;

        round_w10<<<gRW, 256>>>(sqW + i * DD, skW + i * DD, svW + i * DD, soW + i * DD,
                                cqW + i * DD, ckW + i * DD, cvW + i * DD, coW + i * DD,
                                f1W + (size_t)i * DFF * D, f2W + (size_t)i * D * DFF, wh);

        gemv_ada<<<6 * D / 8, 256>>>(ts, adaW_i, adab_i, mods);

        // --- self attention ---
        ln_mod_kernel<<<L, 256>>>(x, mods, 0, D, hx);
        gemm_f16<<<gQKV, 256, GEMM_SMEM>>>(hx, hx, hx, wh, wh + DD, wh + 2 * DD,
                                           nullptr, nullptr, q, k, v,
                                           L, L, L, D, D, EP_STORE);
        rope_k_transpose<<<gRKT, bTr>>>(k, rope, kt);
        attn_mma<<<gAtt, 256, ATTN_SMEM>>>(q, kt, v, oh, rope, L, scale);
        gemm_f16<<<gD, 256, GEMM_SMEM>>>(oh, oh, oh, wh + 3 * DD, nullptr, nullptr,
                                         sob_i, mods + 2 * D, x, nullptr, nullptr,
                                         L, L, L, D, D, EP_RESID_GATE);

        // --- cross attention (cq + ck + cv fused) ---
        ln_mod_kernel<<<L, 256>>>(x, nullptr, 0, 0, hx);
        gemm_f16<<<gCQKV, 256, GEMM_SMEM>>>(hx, ctxh, ctxh,
                                            wh + 4 * DD, wh + 5 * DD, wh + 6 * DD,
                                            nullptr, nullptr, q, ckb, cvb,
                                            L, SCTX, SCTX, D, D, EP_STORE);
        transpose_k<<<gTrC, bTr>>>(ckb, kt, SCTX);
        attn_mma<<<gAtt, 256, ATTN_SMEM>>>(q, kt, cvb, oh, nullptr, SCTX, scale);
        gemm_f16<<<gD, 256, GEMM_SMEM>>>(oh, oh, oh, wh + 7 * DD, nullptr, nullptr,
                                         cob_i, nullptr, x, nullptr, nullptr,
                                         L, L, L, D, D, EP_RESID);

        // --- MLP ---
        ln_mod_kernel<<<L, 256>>>(x, mods, 3 * D, 4 * D, hx);
        gemm_f16<<<gDFF, 256, GEMM_SMEM>>>(hx, hx, hx, wh + 8 * DD, nullptr, nullptr,
                                           f1b_i, nullptr, hb, nullptr, nullptr,
                                           L, L, L, DFF, D, EP_GELU);
        gemm_f16<<<gD, 256, GEMM_SMEM>>>(hb, hb, hb, wh + 12 * DD, nullptr, nullptr,
                                         f2b_i, mods + 5 * D, x, nullptr, nullptr,
                                         L, L, L, D, DFF, EP_RESID_GATE);
    }
}

// round 16
// speedup vs baseline: 1.1947x; 1.1947x over previous
#include <cuda_runtime.h>
#include <cuda_fp16.h>
#include <math.h>
#include <stdint.h>

// Problem constants
constexpr int L    = 3072;
constexpr int D    = 1024;
constexpr int H    = 16;
constexpr int HD   = 64;
constexpr int SCTX = 512;
constexpr int DFF  = 4096;
constexpr int NB   = 2;

// ---------------- scratch (static device arrays; no cudaMalloc allowed) ----
__device__ __half   g_hx [(size_t)L * D];      // LN outputs (GEMM A, fp16)
__device__ float    g_q  [(size_t)L * D];
__device__ float    g_k  [(size_t)L * D];
__device__ float    g_v  [(size_t)L * D];
__device__ __half   g_oh [(size_t)L * D];      // attention outputs (GEMM A, fp16)
__device__ float    g_ck [(size_t)SCTX * D];
__device__ float    g_cv [(size_t)SCTX * D];
__device__ __half   g_hb [(size_t)L * DFF];    // GELU outputs (GEMM A, fp16)
__device__ uint32_t g_kt2[(size_t)H * 32 * L]; // K^T pair-packed half2 [h][d2][l]
__device__ uint32_t g_vp2[(size_t)(L / 2) * D];// V pair-packed half2 [l2][c]
__device__ __half   g_w  [(size_t)16 * D * D]; // fp16 weights, one iter
__device__ __half   g_ctx[(size_t)SCTX * D];   // fp16 context
__device__ float    g_mods[6 * D];

enum { EP_STORE = 0, EP_GELU = 1, EP_RESID = 2, EP_RESID_GATE = 3 };

__device__ __forceinline__ uint32_t h2u(__half2 h) {
    return *reinterpret_cast<uint32_t*>(&h);
}

// fp16 mma m16n8k16, f32 accumulate
__device__ __forceinline__ void mma_f16(float c[4], uint32_t a0, uint32_t a1,
                                        uint32_t a2, uint32_t a3,
                                        uint32_t b0, uint32_t b1) {
    asm volatile(
        "mma.sync.aligned.m16n8k16.row.col.f32.f16.f16.f32 "
        "{%0,%1,%2,%3}, {%4,%5,%6,%7}, {%8,%9}, {%0,%1,%2,%3};"
        : "+f"(c[0]), "+f"(c[1]), "+f"(c[2]), "+f"(c[3])
        : "r"(a0), "r"(a1), "r"(a2), "r"(a3), "r"(b0), "r"(b1));
}

__device__ __forceinline__ void cp_async16(uint32_t saddr, const void* gaddr) {
    asm volatile("cp.async.cg.shared.global [%0], [%1], 16;\n"
                 :: "r"(saddr), "l"(gaddr));
}
__device__ __forceinline__ void cp_commit() {
    asm volatile("cp.async.commit_group;\n");
}
template <int N>
__device__ __forceinline__ void cp_wait() {
    asm volatile("cp.async.wait_group %0;\n" :: "n"(N));
}

// ---------------------------------------------------------------------------
// Weight pre-round: 10 per-iter weight slices -> g_w, fp16 (RN).
// ---------------------------------------------------------------------------
__global__ void __launch_bounds__(256) round_w10(
    const float* s0, const float* s1, const float* s2, const float* s3,
    const float* s4, const float* s5, const float* s6, const float* s7,
    const float* s8, const float* s9, __half* dst)
{
    const int z = blockIdx.z;
    const float* src;
    size_t cnt, off;
    const size_t DD = (size_t)D * D;
    switch (z) {
        case 0: src = s0; cnt = DD;     off = 0;       break;
        case 1: src = s1; cnt = DD;     off = DD;      break;
        case 2: src = s2; cnt = DD;     off = 2 * DD;  break;
        case 3: src = s3; cnt = DD;     off = 3 * DD;  break;
        case 4: src = s4; cnt = DD;     off = 4 * DD;  break;
        case 5: src = s5; cnt = DD;     off = 5 * DD;  break;
        case 6: src = s6; cnt = DD;     off = 6 * DD;  break;
        case 7: src = s7; cnt = DD;     off = 7 * DD;  break;
        case 8: src = s8; cnt = 4 * DD; off = 8 * DD;  break;
        default: src = s9; cnt = 4 * DD; off = 12 * DD; break;
    }
    const size_t i = ((size_t)blockIdx.x * 256 + threadIdx.x) * 4;
    if (i >= cnt) return;
    float4 v = *reinterpret_cast<const float4*>(src + i);
    __half2* d2 = reinterpret_cast<__half2*>(dst + off + i);
    d2[0] = __floats2half2_rn(v.x, v.y);
    d2[1] = __floats2half2_rn(v.z, v.w);
}

// context round to fp16
__global__ void __launch_bounds__(256) round_arr(
    const float* __restrict__ src, __half* __restrict__ dst, size_t n4)
{
    const size_t i = ((size_t)blockIdx.x * 256 + threadIdx.x) * 4;
    if (i >= n4 * 4) return;
    float4 v = *reinterpret_cast<const float4*>(src + i);
    __half2* d2 = reinterpret_cast<__half2*>(dst + i);
    d2[0] = __floats2half2_rn(v.x, v.y);
    d2[1] = __floats2half2_rn(v.z, v.w);
}

// ---------------------------------------------------------------------------
// V pair-pack: V [Lk x D] float -> VP2 [Lk/2 x D] half2(V[2l2][c], V[2l2+1][c])
// thread handles 4 consecutive c.
// ---------------------------------------------------------------------------
__global__ void __launch_bounds__(256) pack_v(
    const float* __restrict__ V, uint32_t* __restrict__ VP2, int Lk)
{
    const size_t i = (size_t)blockIdx.x * 256 + threadIdx.x;
    const size_t nEl = (size_t)(Lk / 2) * (D / 4);
    if (i >= nEl) return;
    const size_t l2 = i / (D / 4);
    const int    c4 = (int)(i % (D / 4)) * 4;
    float4 r0 = *reinterpret_cast<const float4*>(&V[(2 * l2    ) * D + c4]);
    float4 r1 = *reinterpret_cast<const float4*>(&V[(2 * l2 + 1) * D + c4]);
    uint32_t* dst = &VP2[l2 * D + c4];
    dst[0] = h2u(__floats2half2_rn(r0.x, r1.x));
    dst[1] = h2u(__floats2half2_rn(r0.y, r1.y));
    dst[2] = h2u(__floats2half2_rn(r0.z, r1.z));
    dst[3] = h2u(__floats2half2_rn(r0.w, r1.w));
}

// ---------------------------------------------------------------------------
// FP16 tensor-core GEMM (m16n8k16), 4-stage cp.async, BK=32 halves (R15).
// ---------------------------------------------------------------------------
constexpr int GSTAGES = 4;
constexpr int GBKH    = 32;
constexpr int GSW     = 20;
constexpr int GTILE_W = 128 * GSW;
constexpr int GEMM_SMEM = 2 * GSTAGES * GTILE_W * 4; // 81920 bytes

__global__ void __launch_bounds__(256, 2) gemm_f16(
    const __half* __restrict__ A0, const __half* __restrict__ A1,
    const __half* __restrict__ A2,
    const __half* __restrict__ W0, const __half* __restrict__ W1,
    const __half* __restrict__ W2,
    const float* __restrict__ bias, const float* __restrict__ gate,
    void* __restrict__ C0, void* __restrict__ C1, void* __restrict__ C2,
    int M0, int M1, int M2, int N, int K, int mode)
{
    extern __shared__ float smem[];
    float* As = smem;
    float* Bs = smem + GSTAGES * GTILE_W;

    const __half* A = (blockIdx.z == 0) ? A0 : (blockIdx.z == 1) ? A1 : A2;
    const __half* W = (blockIdx.z == 0) ? W0 : (blockIdx.z == 1) ? W1 : W2;
    void*         C = (blockIdx.z == 0) ? C0 : (blockIdx.z == 1) ? C1 : C2;
    const int     M = (blockIdx.z == 0) ? M0 : (blockIdx.z == 1) ? M1 : M2;

    const int m0 = blockIdx.y * 128;
    if (m0 >= M) return;
    const int n0 = blockIdx.x * 128;

    const int tid  = threadIdx.x;
    const int lane = tid & 31;
    const int warp = tid >> 5;
    const int mwb  = (warp & 1) * 64;
    const int nwb  = (warp >> 1) * 32;
    const int qr   = lane >> 2;
    const int qc   = lane & 3;

    const uint32_t sA0 = (uint32_t)__cvta_generic_to_shared(As);
    const uint32_t sB0 = (uint32_t)__cvta_generic_to_shared(Bs);

    const int lrow = tid >> 1;
    const int lc0  = (tid & 1) * 2;

    float acc[4][4][4];
#pragma unroll
    for (int i = 0; i < 4; i++)
#pragma unroll
        for (int j = 0; j < 4; j++)
#pragma unroll
            for (int e = 0; e < 4; e++) acc[i][j][e] = 0.f;

    const int nT = K / GBKH;

    auto ld_stage = [&](int slot, int t) {
        const int kb = t * GBKH;
#pragma unroll
        for (int i = 0; i < 2; i++) {
            const int c = lc0 + i;
            const uint32_t off = (uint32_t)((slot * 128 + lrow) * GSW + c * 4) * 4u;
            cp_async16(sA0 + off, &A[(size_t)(m0 + lrow) * K + kb + c * 8]);
            cp_async16(sB0 + off, &W[(size_t)(n0 + lrow) * K + kb + c * 8]);
        }
    };

#pragma unroll
    for (int s = 0; s < GSTAGES - 1; s++) {
        if (s < nT) ld_stage(s, s);
        cp_commit();
    }

    int slot = 0;
    for (int t = 0; t < nT; t++) {
        cp_wait<GSTAGES - 2>();
        __syncthreads();

        {
            int ns = slot + GSTAGES - 1; if (ns >= GSTAGES) ns -= GSTAGES;
            if (t + GSTAGES - 1 < nT) ld_stage(ns, t + GSTAGES - 1);
            cp_commit();
        }

        const float* At = As + slot * GTILE_W + mwb * GSW;
        const float* Bt = Bs + slot * GTILE_W + nwb * GSW;

#pragma unroll
        for (int ks = 0; ks < 2; ks++) {
            const int kk = ks * 8;
            uint32_t afr[4][4], bfr[4][2];
#pragma unroll
            for (int mt = 0; mt < 4; mt++) {
                const int mb = mt * 16;
                afr[mt][0] = __float_as_uint(At[(mb + qr    ) * GSW + kk + qc    ]);
                afr[mt][1] = __float_as_uint(At[(mb + qr + 8) * GSW + kk + qc    ]);
                afr[mt][2] = __float_as_uint(At[(mb + qr    ) * GSW + kk + qc + 4]);
                afr[mt][3] = __float_as_uint(At[(mb + qr + 8) * GSW + kk + qc + 4]);
            }
#pragma unroll
            for (int nt = 0; nt < 4; nt++) {
                const int nb = nt * 8;
                bfr[nt][0] = __float_as_uint(Bt[(nb + qr) * GSW + kk + qc    ]);
                bfr[nt][1] = __float_as_uint(Bt[(nb + qr) * GSW + kk + qc + 4]);
            }
#pragma unroll
            for (int mt = 0; mt < 4; mt++)
#pragma unroll
                for (int nt = 0; nt < 4; nt++)
                    mma_f16(acc[mt][nt], afr[mt][0], afr[mt][1], afr[mt][2],
                            afr[mt][3], bfr[nt][0], bfr[nt][1]);
        }

        if (++slot >= GSTAGES) slot = 0;
    }

#pragma unroll
    for (int mt = 0; mt < 4; mt++) {
#pragma unroll
        for (int nt = 0; nt < 4; nt++) {
#pragma unroll
            for (int half_ = 0; half_ < 2; half_++) {
                const int r = m0 + mwb + mt * 16 + qr + half_ * 8;
#pragma unroll
                for (int e = 0; e < 2; e++) {
                    const int c = n0 + nwb + nt * 8 + 2 * qc + e;
                    float val = acc[mt][nt][half_ * 2 + e];
                    val += bias ? bias[c] : 0.f;
                    const size_t idx = (size_t)r * N + c;
                    if (mode == EP_STORE) {
                        ((float*)C)[idx] = val;
                    } else if (mode == EP_GELU) {
                        ((__half*)C)[idx] = __float2half_rn(
                            0.5f * val * (1.f + erff(val * 0.70710678118654752f)));
                    } else if (mode == EP_RESID) {
                        ((float*)C)[idx] += val;
                    } else {
                        ((float*)C)[idx] += gate[c] * val;
                    }
                }
            }
        }
    }
}

// ---------------------------------------------------------------------------
// adaLN modulation GEMV
// ---------------------------------------------------------------------------
__global__ void __launch_bounds__(256) gemv_ada(
    const float* __restrict__ t, const float* __restrict__ Wt,
    const float* __restrict__ b, float* __restrict__ out)
{
    const int o    = blockIdx.x * 8 + (threadIdx.x >> 5);
    const int lane = threadIdx.x & 31;
    const float* wr = Wt + (size_t)o * D;
    float s = 0.f;
    for (int d = lane; d < D; d += 32) s = fmaf(t[d], wr[d], s);
#pragma unroll
    for (int off = 16; off; off >>= 1) s += __shfl_xor_sync(0xffffffffu, s, off);
    if (lane == 0) out[o] = s + b[o];
}

// ---------------------------------------------------------------------------
// LayerNorm (+ optional adaLN shift/scale); output fp16
// ---------------------------------------------------------------------------
__global__ void __launch_bounds__(256) ln_mod_kernel(
    const float* __restrict__ x, const float* __restrict__ mods,
    int sh_off, int sc_off, __half* __restrict__ y)
{
    __shared__ float red[8];
    __shared__ float bval;
    const int row = blockIdx.x;
    const int t = threadIdx.x;
    const float* xr = x + (size_t)row * D;

    float v[4];
    float s = 0.f;
#pragma unroll
    for (int j = 0; j < 4; j++) { v[j] = xr[t + j * 256]; s += v[j]; }
#pragma unroll
    for (int off = 16; off; off >>= 1) s += __shfl_xor_sync(0xffffffffu, s, off);
    if ((t & 31) == 0) red[t >> 5] = s;
    __syncthreads();
    if (t == 0) {
        float tot = 0.f;
        for (int j = 0; j < 8; j++) tot += red[j];
        bval = tot * (1.f / D);
    }
    __syncthreads();
    const float mean = bval;

    float vs = 0.f;
#pragma unroll
    for (int j = 0; j < 4; j++) { float d = v[j] - mean; vs = fmaf(d, d, vs); }
#pragma unroll
    for (int off = 16; off; off >>= 1) vs += __shfl_xor_sync(0xffffffffu, vs, off);
    if ((t & 31) == 0) red[t >> 5] = vs;
    __syncthreads();
    if (t == 0) {
        float tot = 0.f;
        for (int j = 0; j < 8; j++) tot += red[j];
        bval = rsqrtf(tot * (1.f / D) + 1e-6f);
    }
    __syncthreads();
    const float rstd = bval;

    __half* yr = y + (size_t)row * D;
#pragma unroll
    for (int j = 0; j < 4; j++) {
        const int d = t + j * 256;
        const float sc = mods ? mods[sc_off + d] : 0.f;
        const float sh = mods ? mods[sh_off + d] : 0.f;
        yr[d] = __float2half_rn((v[j] - mean) * rstd * (1.f + sc) + sh);
    }
}

// ---------------------------------------------------------------------------
// Fused RoPE(K) + transpose + pair-pack: k [L x D] -> KT2 [h][d2][L] half2.
// ---------------------------------------------------------------------------
__global__ void __launch_bounds__(256) rope_k_transpose(
    const float* __restrict__ k, const float* __restrict__ rope,
    uint32_t* __restrict__ KT2)
{
    __shared__ float s[32][65];
    const int h  = blockIdx.y;
    const int l0 = blockIdx.x * 32;
    const int tx = threadIdx.x, ty = threadIdx.y;

#pragma unroll
    for (int jl = 0; jl < 4; jl++) {
        const int l  = ty + jl * 8;
        const int gl = l0 + l;
        const float v1 = k[(size_t)gl * D + h * HD + tx];
        const float v2 = k[(size_t)gl * D + h * HD + tx + 32];
        const float a1 = rope[gl * HD + tx];
        const float a2 = rope[gl * HD + tx + 32];
        s[l][tx]      = v1 * cosf(a1) - v2 * sinf(a1);
        s[l][tx + 32] = v2 * cosf(a2) + v1 * sinf(a2);
    }
    __syncthreads();

#pragma unroll
    for (int jd = 0; jd < 4; jd++) {
        const int d2 = ty + jd * 8;                       // 0..31
        KT2[((size_t)h * 32 + d2) * L + l0 + tx] =
            h2u(__floats2half2_rn(s[tx][2 * d2], s[tx][2 * d2 + 1]));
    }
}

// ---------------------------------------------------------------------------
// Plain K transpose + pair-pack (cross-attention; no rope)
// ---------------------------------------------------------------------------
__global__ void __launch_bounds__(256) transpose_k(
    const float* __restrict__ Kin, uint32_t* __restrict__ KT2, int Lk)
{
    __shared__ float t[32][33];
    const int h  = blockIdx.z;
    const int d0 = blockIdx.y * 32;
    const int l0 = blockIdx.x * 32;
    const int tx = threadIdx.x, ty = threadIdx.y;
#pragma unroll
    for (int j = 0; j < 4; j++)
        t[ty + j * 8][tx] = Kin[(size_t)(l0 + ty + j * 8) * D + h * HD + d0 + tx];
    __syncthreads();
#pragma unroll
    for (int j = 0; j < 2; j++) {
        const int d2l = ty + j * 8;                       // 0..15
        KT2[((size_t)h * 32 + d0 / 2 + d2l) * Lk + l0 + tx] =
            h2u(__floats2half2_rn(t[tx][2 * d2l], t[tx][2 * d2l + 1]));
    }
}

// ---------------------------------------------------------------------------
// FP16 tensor-core flash attention, cp.async overlap, 128 queries/block.
// KT2: pair-packed K^T [h][d2][Lk]; VP2: pair-packed V [l2][D] (col h*64).
// Smem: Ks2 [2][32][72], Vs2 [32][72], Ps2 [128][36] (all half2/uint words).
// Optional fused RoPE on Q. O output fp16.
// ---------------------------------------------------------------------------
constexpr int ATTN_SMEM = (2 * 32 * 72 + 32 * 72 + 128 * 36) * 4;  // 46080 B

__global__ void __launch_bounds__(256, 2) attn_mma(
    const float* __restrict__ Q, const uint32_t* __restrict__ KT2,
    const uint32_t* __restrict__ VP2, __half* __restrict__ O,
    const float* __restrict__ ropePtr, int Lk, float scale)
{
    extern __shared__ uint32_t smu[];
    uint32_t* Ks2 = smu;                     // [2][32][72]
    uint32_t* Vs2 = smu + 2 * 32 * 72;       // [32][72]
    uint32_t* Ps2 = smu + 3 * 32 * 72;       // [128][36]

    const int tid  = threadIdx.x;
    const int warp = tid >> 5;
    const int lane = tid & 31;
    const int qr = lane >> 2, qc = lane & 3;
    const int h  = blockIdx.y;
    const int q0 = blockIdx.x * 128;
    const int row0 = warp * 16;

    const uint32_t* KTh = KT2 + (size_t)h * 32 * Lk;
    const uint32_t sKs = (uint32_t)__cvta_generic_to_shared(Ks2);
    const uint32_t sVs = (uint32_t)__cvta_generic_to_shared(Vs2);

    // issue K[0]: 32 rows x 64 half2 = 512 16B-chunks
    for (int i = tid; i < 512; i += 256) {
        const int r = i >> 4, c4 = (i & 15) * 4;
        cp_async16(sKs + (uint32_t)(r * 72 + c4) * 4u, &KTh[(size_t)r * Lk + c4]);
    }
    cp_commit();

    // stage Q into Ps2 (optional fused RoPE), scaled, fp16 pairs
    if (ropePtr) {
        for (int i = tid; i < 128 * 8; i += 256) {
            const int r = i >> 3, j4 = (i & 7) * 4;
            const int gl = q0 + r;
            float4 q1 = *reinterpret_cast<const float4*>(&Q[(size_t)gl * D + h * HD + j4]);
            float4 q2 = *reinterpret_cast<const float4*>(&Q[(size_t)gl * D + h * HD + j4 + 32]);
            float4 a1 = *reinterpret_cast<const float4*>(&ropePtr[gl * HD + j4]);
            float4 a2 = *reinterpret_cast<const float4*>(&ropePtr[gl * HD + j4 + 32]);
            const float lo0 = (q1.x * cosf(a1.x) - q2.x * sinf(a1.x)) * scale;
            const float lo1 = (q1.y * cosf(a1.y) - q2.y * sinf(a1.y)) * scale;
            const float lo2 = (q1.z * cosf(a1.z) - q2.z * sinf(a1.z)) * scale;
            const float lo3 = (q1.w * cosf(a1.w) - q2.w * sinf(a1.w)) * scale;
            const float hi0 = (q2.x * cosf(a2.x) + q1.x * sinf(a2.x)) * scale;
            const float hi1 = (q2.y * cosf(a2.y) + q1.y * sinf(a2.y)) * scale;
            const float hi2 = (q2.z * cosf(a2.z) + q1.z * sinf(a2.z)) * scale;
            const float hi3 = (q2.w * cosf(a2.w) + q1.w * sinf(a2.w)) * scale;
            Ps2[r * 36 + j4 / 2     ] = h2u(__floats2half2_rn(lo0, lo1));
            Ps2[r * 36 + j4 / 2 + 1 ] = h2u(__floats2half2_rn(lo2, lo3));
            Ps2[r * 36 + j4 / 2 + 16] = h2u(__floats2half2_rn(hi0, hi1));
            Ps2[r * 36 + j4 / 2 + 17] = h2u(__floats2half2_rn(hi2, hi3));
        }
    } else {
        for (int i = tid; i < 128 * 16; i += 256) {
            const int r = i >> 4, c4 = (i & 15) * 4;
            float4 qv = *reinterpret_cast<const float4*>(&Q[(size_t)(q0 + r) * D + h * HD + c4]);
            Ps2[r * 36 + c4 / 2    ] = h2u(__floats2half2_rn(qv.x * scale, qv.y * scale));
            Ps2[r * 36 + c4 / 2 + 1] = h2u(__floats2half2_rn(qv.z * scale, qv.w * scale));
        }
    }
    __syncthreads();

    // Q fragments in registers: 4 k16-steps
    uint32_t qf[4][4];
#pragma unroll
    for (int ks = 0; ks < 4; ks++) {
        const int kk = ks * 8;
        qf[ks][0] = Ps2[(row0 + qr    ) * 36 + kk + qc    ];
        qf[ks][1] = Ps2[(row0 + qr + 8) * 36 + kk + qc    ];
        qf[ks][2] = Ps2[(row0 + qr    ) * 36 + kk + qc + 4];
        qf[ks][3] = Ps2[(row0 + qr + 8) * 36 + kk + qc + 4];
    }

    float m0 = -1e30f, m1 = -1e30f, l0 = 0.f, l1 = 0.f;
    float oacc[8][4];
#pragma unroll
    for (int nt = 0; nt < 8; nt++)
#pragma unroll
        for (int e = 0; e < 4; e++) oacc[nt][e] = 0.f;

    const int nTiles = Lk / 64;
    for (int ti = 0; ti < nTiles; ti++) {
        const int kt = ti * 64;
        uint32_t* Kb = Ks2 + (ti & 1) * 32 * 72;

        cp_wait<0>();        // K[ti] resident (V[ti-1] done earlier)
        __syncthreads();

        // issue V[ti] (pair rows kt/2..kt/2+31), then K[ti+1]
        for (int i = tid; i < 512; i += 256) {
            const int r = i >> 4, c4 = (i & 15) * 4;
            cp_async16(sVs + (uint32_t)(r * 72 + c4) * 4u,
                       &VP2[(size_t)(kt / 2 + r) * D + h * HD + c4]);
        }
        cp_commit();
        if (ti + 1 < nTiles) {
            const uint32_t kb2 = sKs + (uint32_t)(((ti + 1) & 1) * 32 * 72) * 4u;
            for (int i = tid; i < 512; i += 256) {
                const int r = i >> 4, c4 = (i & 15) * 4;
                cp_async16(kb2 + (uint32_t)(r * 72 + c4) * 4u,
                           &KTh[(size_t)r * Lk + kt + 64 + c4]);
            }
        }
        cp_commit();

        // S = Q K^T (4 k16-steps)
        float sf[8][4];
#pragma unroll
        for (int nt = 0; nt < 8; nt++)
#pragma unroll
            for (int e = 0; e < 4; e++) sf[nt][e] = 0.f;
#pragma unroll
        for (int ks = 0; ks < 4; ks++) {
            const int kk = ks * 8;
#pragma unroll
            for (int nt = 0; nt < 8; nt++) {
                const uint32_t b0 = Kb[(kk + qc    ) * 72 + nt * 8 + qr];
                const uint32_t b1 = Kb[(kk + qc + 4) * 72 + nt * 8 + qr];
                mma_f16(sf[nt], qf[ks][0], qf[ks][1], qf[ks][2], qf[ks][3], b0, b1);
            }
        }

        // online softmax
        float rmax0 = -1e30f, rmax1 = -1e30f;
#pragma unroll
        for (int nt = 0; nt < 8; nt++) {
            rmax0 = fmaxf(rmax0, fmaxf(sf[nt][0], sf[nt][1]));
            rmax1 = fmaxf(rmax1, fmaxf(sf[nt][2], sf[nt][3]));
        }
        rmax0 = fmaxf(rmax0, __shfl_xor_sync(0xffffffffu, rmax0, 1));
        rmax0 = fmaxf(rmax0, __shfl_xor_sync(0xffffffffu, rmax0, 2));
        rmax1 = fmaxf(rmax1, __shfl_xor_sync(0xffffffffu, rmax1, 1));
        rmax1 = fmaxf(rmax1, __shfl_xor_sync(0xffffffffu, rmax1, 2));

        const float mn0 = fmaxf(m0, rmax0);
        const float mn1 = fmaxf(m1, rmax1);
        const float a0 = __expf(m0 - mn0);
        const float a1 = __expf(m1 - mn1);
        float rs0 = 0.f, rs1 = 0.f;
#pragma unroll
        for (int nt = 0; nt < 8; nt++) {
            sf[nt][0] = __expf(sf[nt][0] - mn0);
            sf[nt][1] = __expf(sf[nt][1] - mn0);
            sf[nt][2] = __expf(sf[nt][2] - mn1);
            sf[nt][3] = __expf(sf[nt][3] - mn1);
            rs0 += sf[nt][0] + sf[nt][1];
            rs1 += sf[nt][2] + sf[nt][3];
        }
        rs0 += __shfl_xor_sync(0xffffffffu, rs0, 1);
        rs0 += __shfl_xor_sync(0xffffffffu, rs0, 2);
        rs1 += __shfl_xor_sync(0xffffffffu, rs1, 1);
        rs1 += __shfl_xor_sync(0xffffffffu, rs1, 2);
        l0 = l0 * a0 + rs0;
        l1 = l1 * a1 + rs1;
        m0 = mn0; m1 = mn1;
#pragma unroll
        for (int nt = 0; nt < 8; nt++) {
            oacc[nt][0] *= a0; oacc[nt][1] *= a0;
            oacc[nt][2] *= a1; oacc[nt][3] *= a1;
        }

        // P -> warp-private Ps2 rows (fp16 pairs; k2 = nt*4+qc)
        __syncwarp();
#pragma unroll
        for (int nt = 0; nt < 8; nt++) {
            Ps2[(row0 + qr    ) * 36 + nt * 4 + qc] = h2u(__floats2half2_rn(sf[nt][0], sf[nt][1]));
            Ps2[(row0 + qr + 8) * 36 + nt * 4 + qc] = h2u(__floats2half2_rn(sf[nt][2], sf[nt][3]));
        }
        __syncwarp();

        // V[ti] landed? (K[ti+1] may still be in flight)
        cp_wait<1>();
        __syncthreads();

        // O += P V (4 k16-steps over 64 keys)
#pragma unroll
        for (int ks = 0; ks < 4; ks++) {
            const int kk = ks * 8;
            const uint32_t pa0 = Ps2[(row0 + qr    ) * 36 + kk + qc    ];
            const uint32_t pa1 = Ps2[(row0 + qr + 8) * 36 + kk + qc    ];
            const uint32_t pa2 = Ps2[(row0 + qr    ) * 36 + kk + qc + 4];
            const uint32_t pa3 = Ps2[(row0 + qr + 8) * 36 + kk + qc + 4];
#pragma unroll
            for (int nt = 0; nt < 8; nt++) {
                const uint32_t b0 = Vs2[(kk + qc    ) * 72 + nt * 8 + qr];
                const uint32_t b1 = Vs2[(kk + qc + 4) * 72 + nt * 8 + qr];
                mma_f16(oacc[nt], pa0, pa1, pa2, pa3, b0, b1);
            }
        }
    }

    // epilogue: O in fp16
    const float inv0 = 1.f / l0;
    const float inv1 = 1.f / l1;
#pragma unroll
    for (int nt = 0; nt < 8; nt++) {
        __half2 w0 = __floats2half2_rn(oacc[nt][0] * inv0, oacc[nt][1] * inv0);
        __half2 w1 = __floats2half2_rn(oacc[nt][2] * inv1, oacc[nt][3] * inv1);
        *reinterpret_cast<__half2*>(&O[(size_t)(q0 + row0 + qr    ) * D + h * HD + nt * 8 + 2 * qc]) = w0;
        *reinterpret_cast<__half2*>(&O[(size_t)(q0 + row0 + qr + 8) * D + h * HD + nt * 8 + 2 * qc]) = w1;
    }
}

// ---------------------------------------------------------------------------
extern "C" void kernel_launch(void* const* d_in, const int* in_sizes, int n_in,
                              void* d_out, int out_size)
{
    const float* x_in = (const float*)d_in[0];
    const float* ts   = (const float*)d_in[1];
    const float* ctx  = (const float*)d_in[2];
    const float* rope = (const float*)d_in[3];
    const float* adaW = (const float*)d_in[4];
    const float* adab = (const float*)d_in[5];
    const float* sqW  = (const float*)d_in[6];
    const float* skW  = (const float*)d_in[7];
    const float* svW  = (const float*)d_in[8];
    const float* soW  = (const float*)d_in[9];
    const float* sob  = (const float*)d_in[10];
    const float* cqW  = (const float*)d_in[11];
    const float* ckW  = (const float*)d_in[12];
    const float* cvW  = (const float*)d_in[13];
    const float* coW  = (const float*)d_in[14];
    const float* cob  = (const float*)d_in[15];
    const float* f1W  = (const float*)d_in[16];
    const float* f1b  = (const float*)d_in[17];
    const float* f2W  = (const float*)d_in[18];
    const float* f2b  = (const float*)d_in[19];

    float* x = (float*)d_out;

    __half *hx, *oh, *hb, *wh, *ctxh;
    float *q, *k, *v, *ckb, *cvb, *mods;
    uint32_t *kt2, *vp2;
    cudaGetSymbolAddress((void**)&hx,   g_hx);
    cudaGetSymbolAddress((void**)&q,    g_q);
    cudaGetSymbolAddress((void**)&k,    g_k);
    cudaGetSymbolAddress((void**)&v,    g_v);
    cudaGetSymbolAddress((void**)&oh,   g_oh);
    cudaGetSymbolAddress((void**)&ckb,  g_ck);
    cudaGetSymbolAddress((void**)&cvb,  g_cv);
    cudaGetSymbolAddress((void**)&hb,   g_hb);
    cudaGetSymbolAddress((void**)&kt2,  g_kt2);
    cudaGetSymbolAddress((void**)&vp2,  g_vp2);
    cudaGetSymbolAddress((void**)&wh,   g_w);
    cudaGetSymbolAddress((void**)&ctxh, g_ctx);
    cudaGetSymbolAddress((void**)&mods, g_mods);

    cudaFuncSetAttribute(attn_mma, cudaFuncAttributeMaxDynamicSharedMemorySize, ATTN_SMEM);
    cudaFuncSetAttribute(gemm_f16, cudaFuncAttributeMaxDynamicSharedMemorySize, GEMM_SMEM);

    cudaMemcpyAsync(x, x_in, (size_t)L * D * sizeof(float), cudaMemcpyDeviceToDevice);

    const size_t DD = (size_t)D * D;
    const float scale = 0.125f; // 64^-0.5
    const dim3 gQKV(D   / 128, L / 128, 3);
    const dim3 gD  (D   / 128, L / 128, 1);
    const dim3 gDFF(DFF / 128, L / 128, 1);
    const dim3 gCQKV(D  / 128, L / 128, 3);
    const dim3 gAtt(L / 128, H);
    const dim3 gRKT(L / 32, H);
    const dim3 gTrC(SCTX / 32, HD / 32, H);
    const dim3 bTr(32, 8);
    const dim3 gRW((4 * DD) / 1024, 1, 10);
    const int  gPVs = (int)(((size_t)(L    / 2) * (D / 4) + 255) / 256);
    const int  gPVc = (int)(((size_t)(SCTX / 2) * (D / 4) + 255) / 256);

    // pre-round context once
    round_arr<<<(SCTX * D) / 1024, 256>>>(ctx, ctxh, (size_t)(SCTX * D) / 4);

    for (int i = 0; i < NB; i++) {
        const float* adaW_i = adaW + (size_t)i * 6 * DD;
        const float* adab_i = adab + (size_t)i * 6 * D;
        const float* sob_i  = sob  + (size_t)i * D;
        const float* cob_i  = cob  + (size_t)i * D;
        const float* f1b_i  = f1b  + (size_t)i * DFF;
        const float* f2b_i  = f2b  + (size_t)i * D;

        round_w10<<<gRW, 256>>>(sqW + i * DD, skW + i * DD, svW + i * DD, soW + i * DD,
                                cqW + i * DD, ckW + i * DD, cvW + i * DD, coW + i * DD,
                                f1W + (size_t)i * DFF * D, f2W + (size_t)i * D * DFF, wh);

        gemv_ada<<<6 * D / 8, 256>>>(ts, adaW_i, adab_i, mods);

        // --- self attention ---
        ln_mod_kernel<<<L, 256>>>(x, mods, 0, D, hx);
        gemm_f16<<<gQKV, 256, GEMM_SMEM>>>(hx, hx, hx, wh, wh + DD, wh + 2 * DD,
                                           nullptr, nullptr, q, k, v,
                                           L, L, L, D, D, EP_STORE);
        rope_k_transpose<<<gRKT, bTr>>>(k, rope, kt2);
        pack_v<<<gPVs, 256>>>(v, vp2, L);
        attn_mma<<<gAtt, 256, ATTN_SMEM>>>(q, kt2, vp2, oh, rope, L, scale);
        gemm_f16<<<gD, 256, GEMM_SMEM>>>(oh, oh, oh, wh + 3 * DD, nullptr, nullptr,
                                         sob_i, mods + 2 * D, x, nullptr, nullptr,
                                         L, L, L, D, D, EP_RESID_GATE);

        // --- cross attention (cq + ck + cv fused) ---
        ln_mod_kernel<<<L, 256>>>(x, nullptr, 0, 0, hx);
        gemm_f16<<<gCQKV, 256, GEMM_SMEM>>>(hx, ctxh, ctxh,
                                            wh + 4 * DD, wh + 5 * DD, wh + 6 * DD,
                                            nullptr, nullptr, q, ckb, cvb,
                                            L, SCTX, SCTX, D, D, EP_STORE);
        transpose_k<<<gTrC, bTr>>>(ckb, kt2, SCTX);
        pack_v<<<gPVc, 256>>>(cvb, vp2, SCTX);
        attn_mma<<<gAtt, 256, ATTN_SMEM>>>(q, kt2, vp2, oh, nullptr, SCTX, scale);
        gemm_f16<<<gD, 256, GEMM_SMEM>>>(oh, oh, oh, wh + 7 * DD, nullptr, nullptr,
                                         cob_i, nullptr, x, nullptr, nullptr,
                                         L, L, L, D, D, EP_RESID);

        // --- MLP ---
        ln_mod_kernel<<<L, 256>>>(x, mods, 3 * D, 4 * D, hx);
        gemm_f16<<<gDFF, 256, GEMM_SMEM>>>(hx, hx, hx, wh + 8 * DD, nullptr, nullptr,
                                           f1b_i, nullptr, hb, nullptr, nullptr,
                                           L, L, L, DFF, D, EP_GELU);
        gemm_f16<<<gD, 256, GEMM_SMEM>>>(hb, hb, hb, wh + 12 * DD, nullptr, nullptr,
                                         f2b_i, mods + 5 * D, x, nullptr, nullptr,
                                         L, L, L, D, DFF, EP_RESID_GATE);
    }
}